// round 13
// baseline (speedup 1.0000x reference)
#include <cuda_runtime.h>
#include <cstdint>

#define NN 768
#define DD 64
#define LN_EPS 1e-5f

__device__ float g_A[NN * DD];  // h[i] @ W_g[64:128]
__device__ float g_B[NN * DD];  // h[j] @ W_g[128:192] + b_g
__device__ float g_S[9];        // LN(z) moment scalars (scaled by 1/64)

#define FFMA2(d, a, b) asm("fma.rn.f32x2 %0, %1, %2, %0;" : "+l"(d) : "l"(a), "l"(b))
#define PACK2(dst, lo, hi) asm("mov.b64 %0, {%1, %2};" : "=l"(dst) : "f"(lo), "f"(hi))
#define UNPACK2(lo, hi, v) asm("mov.b64 {%0, %1}, %2;" : "=f"(lo), "=f"(hi) : "l"(v))

// ---------------------------------------------------------------------------
// Precompute A[i,d], B[i,d], and the 9 LN(z) moment scalars
// ---------------------------------------------------------------------------
__global__ __launch_bounds__(DD) void precompute_kernel(
    const float* __restrict__ h,
    const float* __restrict__ W_g,
    const float* __restrict__ b_g,
    const float* __restrict__ W_r,
    const float* __restrict__ b_r)
{
    __shared__ float hs[DD];
    const int i = blockIdx.x;
    const int d = threadIdx.x;
    hs[d] = h[i * DD + d];
    __syncthreads();
    float a = 0.f, b = 0.f;
#pragma unroll 16
    for (int k = 0; k < DD; k++) {
        float hv = hs[k];
        a = fmaf(hv, W_g[(64 + k) * DD + d], a);
        b = fmaf(hv, W_g[(128 + k) * DD + d], b);
    }
    g_A[i * DD + d] = a;
    g_B[i * DD + d] = b + b_g[d];

    // Block 0: moment scalars for LN(corr @ W_r + b_r)
    if (i == 0) {
        const float w0 = W_r[d], w1 = W_r[64 + d], bb = b_r[d];
        float v[9] = { w0, w1, bb, w0 * w0, w1 * w1, w0 * w1,
                       w0 * bb, w1 * bb, bb * bb };
        __shared__ float red[2][9];
#pragma unroll
        for (int s = 0; s < 9; s++) {
            float x = v[s];
#pragma unroll
            for (int off = 16; off; off >>= 1)
                x += __shfl_xor_sync(0xffffffffu, x, off);
            v[s] = x;
        }
        if ((d & 31) == 0) {
#pragma unroll
            for (int s = 0; s < 9; s++) red[d >> 5][s] = v[s];
        }
        __syncthreads();
        if (d < 9) g_S[d] = (red[0][d] + red[1][d]) * (1.f / 64.f);
    }
}

// ---------------------------------------------------------------------------
// Main kernel: one block per row i; warps process chunks of 8 masked pairs.
// Phase 2: even/odd-k f32x2 split, SINGLE pass over all 8 jj (weights loaded
// once per chunk). Zero MOVs in the inner loop. Phase 3: R9-style 16
// interleaved shuffle chains.
// ---------------------------------------------------------------------------
__global__ __launch_bounds__(256, 3) void gatraj_main_kernel(
    const float* __restrict__ corr,   // [N,N,2]
    const int*   __restrict__ nei,    // [N,N]
    const float* __restrict__ h,      // [N,D]
    const float* __restrict__ cn,     // [N,D]
    const float* __restrict__ W_r,    // [2,D]
    const float* __restrict__ b_r,
    const float* __restrict__ g_r,
    const float* __restrict__ be_r,
    const float* __restrict__ W_g,    // [3D,D] rows 0..63
    const float* __restrict__ g_g,
    const float* __restrict__ be_g,
    const float* __restrict__ be_a,   // [1]
    const float* __restrict__ W_w,    // [D,D]
    const float* __restrict__ b_w,
    const float* __restrict__ g_w,
    const float* __restrict__ be_w,
    float* __restrict__ out)          // [2*N*D]: H_out then C
{
    // wq[m][l] = ( pack(W[2m][l],   W[2m+1][l]),
    //              pack(W[2m][l+32],W[2m+1][l+32]) )   m=0..31, l=0..31
    __shared__ ulonglong2 wq[32][32];           // 16 KB
    __shared__ float Rsm[8][8][64];             // [warp][jj][k]  16 KB
    __shared__ int   list[832];
    __shared__ int   warp_tot[8], warp_off[8], mcount_sh;
    __shared__ float sh_acc[8][64];
    __shared__ float sh_hs[64];
    __shared__ float sh_y[64];

    const int i    = blockIdx.x;
    const int tid  = threadIdx.x;
    const int warp = tid >> 5;
    const int lane = tid & 31;

    const int* neirow = nei + (size_t)i * NN;

    // ---- Stage Wg_r as even/odd-k pairs ----
    for (int idx = tid; idx < 32 * 32; idx += 256) {
        const int m = idx >> 5, l = idx & 31;
        unsigned long long plo, phi;
        PACK2(plo, W_g[(2 * m) * DD + l],      W_g[(2 * m + 1) * DD + l]);
        PACK2(phi, W_g[(2 * m) * DD + l + 32], W_g[(2 * m + 1) * DD + l + 32]);
        ulonglong2 q; q.x = plo; q.y = phi;
        wq[m][l] = q;
    }

    // ---- Deterministic compaction of masked j (sorted order) ----
    {
        const int b3 = tid * 3;
        const int m0 = neirow[b3 + 0] > 0;
        const int m1 = neirow[b3 + 1] > 0;
        const int m2 = neirow[b3 + 2] > 0;
        const int c  = m0 + m1 + m2;
        int s = c;
#pragma unroll
        for (int off = 1; off < 32; off <<= 1) {
            int v = __shfl_up_sync(0xffffffffu, s, off);
            if (lane >= off) s += v;
        }
        if (lane == 31) warp_tot[warp] = s;
        __syncthreads();
        if (tid == 0) {
            int run = 0;
#pragma unroll
            for (int w = 0; w < 8; w++) { warp_off[w] = run; run += warp_tot[w]; }
            mcount_sh = run;
        }
        __syncthreads();
        int pos = warp_off[warp] + s - c;
        if (m0) list[pos++] = b3 + 0;
        if (m1) list[pos++] = b3 + 1;
        if (m2) list[pos++] = b3 + 2;
        const int mc  = mcount_sh;
        const int pad = (mc + 63) & ~63;
        for (int idx = mc + tid; idx < pad; idx += 256) list[idx] = 0;
    }
    __syncthreads();
    const int mcount = mcount_sh;

    // ---- Per-thread constants ----
    const float wr0_lo = W_r[lane],        wr0_hi = W_r[lane + 32];
    const float wr1_lo = W_r[64 + lane],   wr1_hi = W_r[64 + lane + 32];
    const float br_lo  = b_r[lane],        br_hi  = b_r[lane + 32];
    const float gr_lo  = g_r[lane],        gr_hi  = g_r[lane + 32];
    const float ber_lo = be_r[lane],       ber_hi = be_r[lane + 32];
    const float gg_lo  = g_g[lane],        gg_hi  = g_g[lane + 32];
    const float beg_lo = be_g[lane],       beg_hi = be_g[lane + 32];
    const float A_lo   = g_A[i * DD + lane];
    const float A_hi   = g_A[i * DD + lane + 32];
    // analytic LN(z) moment scalars
    const float S0 = g_S[0], S1 = g_S[1], Sb = g_S[2];
    const float Q00 = g_S[3], Q11 = g_S[4], Q01 = g_S[5];
    const float Q0b = g_S[6], Q1b = g_S[7], Qbb = g_S[8];

    const float2* corr2 = (const float2*)corr + (size_t)i * NN;

    float acc_lo = 0.f, acc_hi = 0.f;

    for (int base = warp * 8; base < mcount; base += 64) {

        // ---- Phase 1: r vectors (shuffle-free analytic LN) -> shared ----
#pragma unroll
        for (int jj = 0; jj < 8; jj++) {
            const int j = list[base + jj];
            const float2 c = corr2[j];
            const float z_lo = fmaf(c.x, wr0_lo, fmaf(c.y, wr1_lo, br_lo));
            const float z_hi = fmaf(c.x, wr0_hi, fmaf(c.y, wr1_hi, br_hi));
            const float u   = fmaf(c.x, S0, fmaf(c.y, S1, Sb));
            const float ez2 = fmaf(c.x * c.x, Q00,
                              fmaf(c.y * c.y, Q11,
                              fmaf(2.f * c.x * c.y, Q01,
                              fmaf(2.f * c.x, Q0b,
                              fmaf(2.f * c.y, Q1b, Qbb)))));
            const float rstd = rsqrtf(fmaxf(ez2 - u * u, 0.f) + LN_EPS);
            Rsm[warp][jj][lane]      = fmaxf(fmaf(gr_lo * (z_lo - u), rstd, ber_lo), 0.f);
            Rsm[warp][jj][lane + 32] = fmaxf(fmaf(gr_hi * (z_hi - u), rstd, ber_hi), 0.f);
        }
        __syncwarp();

        // ---- Phase 2: even/odd-k split, all 8 jj in ONE pass ----
        // weights loaded once per chunk; zero MOVs.
        unsigned long long aL[8], aH[8];
#pragma unroll
        for (int jj = 0; jj < 8; jj++) { aL[jj] = 0ull; aH[jj] = 0ull; }
#pragma unroll 4
        for (int t = 0; t < 16; t++) {           // k = 4t..4t+3
            const ulonglong2 w0 = wq[2 * t][lane];      // k = 4t, 4t+1
            const ulonglong2 w1 = wq[2 * t + 1][lane];  // k = 4t+2, 4t+3
#pragma unroll
            for (int jj = 0; jj < 8; jj++) {
                const ulonglong2 rr = *(const ulonglong2*)&Rsm[warp][jj][t * 4];
                // rr.x = (r[4t], r[4t+1]); rr.y = (r[4t+2], r[4t+3])
                FFMA2(aL[jj], rr.x, w0.x);
                FFMA2(aH[jj], rr.x, w0.y);
                FFMA2(aL[jj], rr.y, w1.x);
                FFMA2(aH[jj], rr.y, w1.y);
            }
        }
        __syncwarp();

        // ---- Phase 3: fold halves + A+B, LN + sigmoid gate + accumulate ----
        float ylo[8], yhi[8], s1v[8], s2v[8];
#pragma unroll
        for (int jj = 0; jj < 8; jj++) {
            const int j = list[base + jj];
            float e0, e1;
            UNPACK2(e0, e1, aL[jj]);
            ylo[jj] = e0 + e1 + A_lo + g_B[j * DD + lane];
            UNPACK2(e0, e1, aH[jj]);
            yhi[jj] = e0 + e1 + A_hi + g_B[j * DD + lane + 32];
            s1v[jj] = ylo[jj] + yhi[jj];
            s2v[jj] = ylo[jj] * ylo[jj] + yhi[jj] * yhi[jj];
        }
        // 16 independent butterfly chains — fully interleavable
#pragma unroll
        for (int off = 16; off; off >>= 1) {
#pragma unroll
            for (int jj = 0; jj < 8; jj++) {
                s1v[jj] += __shfl_xor_sync(0xffffffffu, s1v[jj], off);
                s2v[jj] += __shfl_xor_sync(0xffffffffu, s2v[jj], off);
            }
        }
#pragma unroll
        for (int jj = 0; jj < 8; jj++) {
            const float u    = s1v[jj] * (1.f / 64.f);
            const float rstd = rsqrtf(fmaxf(s2v[jj] * (1.f / 64.f) - u * u, 0.f) + LN_EPS);
            const float t_lo = fmaf(gg_lo * (ylo[jj] - u), rstd, beg_lo);
            const float t_hi = fmaf(gg_hi * (yhi[jj] - u), rstd, beg_hi);
            const float gate_lo = 1.f / (1.f + __expf(-t_lo));
            const float gate_hi = 1.f / (1.f + __expf(-t_hi));
            const int j = list[base + jj];
            const float hj_lo = h[j * DD + lane];
            const float hj_hi = h[j * DD + lane + 32];
            if (base + jj < mcount) {            // predicated accumulate only
                acc_lo = fmaf(hj_lo, gate_lo, acc_lo);
                acc_hi = fmaf(hj_hi, gate_hi, acc_hi);
            }
        }
    }

    sh_acc[warp][lane]      = acc_lo;
    sh_acc[warp][lane + 32] = acc_hi;
    __syncthreads();

    // ---- Block reduce + Pos scale (Pos = 1/mcount if relu(be_a)>0 else 1/N) ----
    if (tid < 64) {
        float s = 0.f;
#pragma unroll
        for (int w = 0; w < 8; w++) s += sh_acc[w][tid];
        const float rba   = fmaxf(be_a[0], 0.f);
        const float scale = (rba > 0.f) ? (1.f / (float)(mcount > 0 ? mcount : 1))
                                        : (1.f / (float)NN);
        sh_hs[tid] = s * scale;
    }
    __syncthreads();

    // ---- Epilogue: relu(LN(H_sum @ W_w + b_w)) + cn; tanh ----
    if (tid < 64) {
        float y = b_w[tid];
#pragma unroll 16
        for (int k = 0; k < 64; k++)
            y = fmaf(sh_hs[k], W_w[k * DD + tid], y);
        sh_y[tid] = y;
    }
    __syncthreads();

    if (tid < 64) {
        float s1 = 0.f, s2 = 0.f;
#pragma unroll 16
        for (int k = 0; k < 64; k++) {
            const float v = sh_y[k];
            s1 += v;
            s2 += v * v;
        }
        const float u    = s1 * (1.f / 64.f);
        const float rstd = rsqrtf(fmaxf(s2 * (1.f / 64.f) - u * u, 0.f) + LN_EPS);
        const float y    = sh_y[tid];
        const float hsum = fmaxf(fmaf(g_w[tid] * (y - u), rstd, be_w[tid]), 0.f);
        const float Cv   = hsum + cn[i * DD + tid];
        const float Hout = h[i * DD + tid] + tanhf(Cv);
        out[i * DD + tid]           = Hout;
        out[NN * DD + i * DD + tid] = Cv;
    }
}

// ---------------------------------------------------------------------------
extern "C" void kernel_launch(void* const* d_in, const int* in_sizes, int n_in,
                              void* d_out, int out_size)
{
    const float* corr = (const float*)d_in[0];
    const int*   nei  = (const int*)d_in[1];
    const float* h    = (const float*)d_in[3];
    const float* cn   = (const float*)d_in[4];
    const float* W_r  = (const float*)d_in[5];
    const float* b_r  = (const float*)d_in[6];
    const float* g_r  = (const float*)d_in[7];
    const float* be_r = (const float*)d_in[8];
    const float* W_g  = (const float*)d_in[9];
    const float* b_g  = (const float*)d_in[10];
    const float* g_g  = (const float*)d_in[11];
    const float* be_g = (const float*)d_in[12];
    const float* be_a = (const float*)d_in[16];
    const float* W_w  = (const float*)d_in[17];
    const float* b_w  = (const float*)d_in[18];
    const float* g_w  = (const float*)d_in[19];
    const float* be_w = (const float*)d_in[20];
    float* out = (float*)d_out;

    precompute_kernel<<<NN, DD>>>(h, W_g, b_g, W_r, b_r);
    gatraj_main_kernel<<<NN, 256>>>(corr, nei, h, cn,
                                    W_r, b_r, g_r, be_r,
                                    W_g, g_g, be_g, be_a,
                                    W_w, b_w, g_w, be_w, out);
}

// round 14
// speedup vs baseline: 1.0847x; 1.0847x over previous
#include <cuda_runtime.h>
#include <cstdint>

#define NN 768
#define DD 64
#define LN_EPS 1e-5f

__device__ float g_A[NN * DD];  // h[i] @ W_g[64:128]
__device__ float g_B[NN * DD];  // h[j] @ W_g[128:192] + b_g
__device__ float g_S[9];        // LN(z) moment scalars (scaled by 1/64)

#define FFMA2(d, a, b) asm("fma.rn.f32x2 %0, %1, %2, %0;" : "+l"(d) : "l"(a), "l"(b))
#define PACK2(dst, lo, hi) asm("mov.b64 %0, {%1, %2};" : "=l"(dst) : "f"(lo), "f"(hi))
#define DUP2(dst, v)       asm("mov.b64 %0, {%1, %1};" : "=l"(dst) : "f"(v))
#define UNPACK2(lo, hi, v) asm("mov.b64 {%0, %1}, %2;" : "=f"(lo), "=f"(hi) : "l"(v))

// ---------------------------------------------------------------------------
// Precompute A[i,d], B[i,d], and the 9 LN(z) moment scalars
// ---------------------------------------------------------------------------
__global__ __launch_bounds__(DD) void precompute_kernel(
    const float* __restrict__ h,
    const float* __restrict__ W_g,
    const float* __restrict__ b_g,
    const float* __restrict__ W_r,
    const float* __restrict__ b_r)
{
    __shared__ float hs[DD];
    const int i = blockIdx.x;
    const int d = threadIdx.x;
    hs[d] = h[i * DD + d];
    __syncthreads();
    float a = 0.f, b = 0.f;
#pragma unroll 16
    for (int k = 0; k < DD; k++) {
        float hv = hs[k];
        a = fmaf(hv, W_g[(64 + k) * DD + d], a);
        b = fmaf(hv, W_g[(128 + k) * DD + d], b);
    }
    g_A[i * DD + d] = a;
    g_B[i * DD + d] = b + b_g[d];

    // Block 0: moment scalars for LN(corr @ W_r + b_r)
    if (i == 0) {
        const float w0 = W_r[d], w1 = W_r[64 + d], bb = b_r[d];
        float v[9] = { w0, w1, bb, w0 * w0, w1 * w1, w0 * w1,
                       w0 * bb, w1 * bb, bb * bb };
        __shared__ float red[2][9];
#pragma unroll
        for (int s = 0; s < 9; s++) {
            float x = v[s];
#pragma unroll
            for (int off = 16; off; off >>= 1)
                x += __shfl_xor_sync(0xffffffffu, x, off);
            v[s] = x;
        }
        if ((d & 31) == 0) {
#pragma unroll
            for (int s = 0; s < 9; s++) red[d >> 5][s] = v[s];
        }
        __syncthreads();
        if (d < 9) g_S[d] = (red[0][d] + red[1][d]) * (1.f / 64.f);
    }
}

struct Smem {
    unsigned long long wsm[64 * 32];  // (w[k][l], w[k][l+32])        16 KB
    float  Rsm[8][8][64];             // [warp][jj][k]                 16 KB
    float  hsm[8][8][64];             // staged h[j] per warp/jj       16 KB
    float2 csm[NN];                   // staged corr row                6 KB
    int    list[832];
    int    warp_tot[8], warp_off[8], mcount;
    float  sh_acc[8][64];
    float  sh_hs[64], sh_y[64];
};

// ---------------------------------------------------------------------------
// Main kernel: R9 structure + latency hiding:
//  - corr row staged to smem at block start (kills cold-DRAM on critical path)
//  - h[j] staged through smem during phase 1 (L2 latency hidden by phase 2)
// ---------------------------------------------------------------------------
__global__ __launch_bounds__(256) void gatraj_main_kernel(
    const float* __restrict__ corr,   // [N,N,2]
    const int*   __restrict__ nei,    // [N,N]
    const float* __restrict__ h,      // [N,D]
    const float* __restrict__ cn,     // [N,D]
    const float* __restrict__ W_r,    // [2,D]
    const float* __restrict__ b_r,
    const float* __restrict__ g_r,
    const float* __restrict__ be_r,
    const float* __restrict__ W_g,    // [3D,D] rows 0..63
    const float* __restrict__ g_g,
    const float* __restrict__ be_g,
    const float* __restrict__ be_a,   // [1]
    const float* __restrict__ W_w,    // [D,D]
    const float* __restrict__ b_w,
    const float* __restrict__ g_w,
    const float* __restrict__ be_w,
    float* __restrict__ out)          // [2*N*D]: H_out then C
{
    extern __shared__ char smem_raw[];
    Smem* S = (Smem*)smem_raw;

    const int i    = blockIdx.x;
    const int tid  = threadIdx.x;
    const int warp = tid >> 5;
    const int lane = tid & 31;

    const int* neirow = nei + (size_t)i * NN;
    const float2* corr2 = (const float2*)corr + (size_t)i * NN;

    // ---- Stage corr row (cold-streamed data) into smem, coalesced ----
#pragma unroll
    for (int idx = tid; idx < NN; idx += 256)
        S->csm[idx] = corr2[idx];

    // ---- Stage Wg_r as packed column pairs ----
    for (int idx = tid; idx < 64 * 32; idx += 256) {
        const int k = idx >> 5, l = idx & 31;
        unsigned long long w;
        PACK2(w, W_g[k * DD + l], W_g[k * DD + l + 32]);
        S->wsm[idx] = w;
    }

    // ---- Deterministic compaction of masked j (sorted order) ----
    {
        const int b3 = tid * 3;
        const int m0 = neirow[b3 + 0] > 0;
        const int m1 = neirow[b3 + 1] > 0;
        const int m2 = neirow[b3 + 2] > 0;
        const int c  = m0 + m1 + m2;
        int s = c;
#pragma unroll
        for (int off = 1; off < 32; off <<= 1) {
            int v = __shfl_up_sync(0xffffffffu, s, off);
            if (lane >= off) s += v;
        }
        if (lane == 31) S->warp_tot[warp] = s;
        __syncthreads();
        if (tid == 0) {
            int run = 0;
#pragma unroll
            for (int w = 0; w < 8; w++) { S->warp_off[w] = run; run += S->warp_tot[w]; }
            S->mcount = run;
        }
        __syncthreads();
        int pos = S->warp_off[warp] + s - c;
        if (m0) S->list[pos++] = b3 + 0;
        if (m1) S->list[pos++] = b3 + 1;
        if (m2) S->list[pos++] = b3 + 2;
        const int mc  = S->mcount;
        const int pad = (mc + 63) & ~63;
        for (int idx = mc + tid; idx < pad; idx += 256) S->list[idx] = 0;
    }
    __syncthreads();
    const int mcount = S->mcount;

    // ---- Per-thread constants ----
    const float wr0_lo = W_r[lane],        wr0_hi = W_r[lane + 32];
    const float wr1_lo = W_r[64 + lane],   wr1_hi = W_r[64 + lane + 32];
    const float br_lo  = b_r[lane],        br_hi  = b_r[lane + 32];
    const float gr_lo  = g_r[lane],        gr_hi  = g_r[lane + 32];
    const float ber_lo = be_r[lane],       ber_hi = be_r[lane + 32];
    const float gg_lo  = g_g[lane],        gg_hi  = g_g[lane + 32];
    const float beg_lo = be_g[lane],       beg_hi = be_g[lane + 32];
    const float A_lo   = g_A[i * DD + lane];
    const float A_hi   = g_A[i * DD + lane + 32];
    // analytic LN(z) moment scalars
    const float S0 = g_S[0], S1 = g_S[1], Sb = g_S[2];
    const float Q00 = g_S[3], Q11 = g_S[4], Q01 = g_S[5];
    const float Q0b = g_S[6], Q1b = g_S[7], Qbb = g_S[8];

    float acc_lo = 0.f, acc_hi = 0.f;

    for (int base = warp * 8; base < mcount; base += 64) {
        unsigned long long yv[8];

        // ---- Phase 1: r vectors (analytic LN) -> shared; stage h[j];
        //      init y with A + B (g_B LDG hidden under phase 2) ----
#pragma unroll
        for (int jj = 0; jj < 8; jj++) {
            const int j = S->list[base + jj];
            const float2 c = S->csm[j];                  // smem, not cold DRAM
            // stage h[j] now; consumed in phase 3 via LDS
            S->hsm[warp][jj][lane]      = h[j * DD + lane];
            S->hsm[warp][jj][lane + 32] = h[j * DD + lane + 32];
            const float z_lo = fmaf(c.x, wr0_lo, fmaf(c.y, wr1_lo, br_lo));
            const float z_hi = fmaf(c.x, wr0_hi, fmaf(c.y, wr1_hi, br_hi));
            const float u   = fmaf(c.x, S0, fmaf(c.y, S1, Sb));
            const float ez2 = fmaf(c.x * c.x, Q00,
                              fmaf(c.y * c.y, Q11,
                              fmaf(2.f * c.x * c.y, Q01,
                              fmaf(2.f * c.x, Q0b,
                              fmaf(2.f * c.y, Q1b, Qbb)))));
            const float rstd = rsqrtf(fmaxf(ez2 - u * u, 0.f) + LN_EPS);
            S->Rsm[warp][jj][lane]      = fmaxf(fmaf(gr_lo * (z_lo - u), rstd, ber_lo), 0.f);
            S->Rsm[warp][jj][lane + 32] = fmaxf(fmaf(gr_hi * (z_hi - u), rstd, ber_hi), 0.f);
            PACK2(yv[jj], A_lo + g_B[j * DD + lane], A_hi + g_B[j * DD + lane + 32]);
        }
        __syncwarp();

        // ---- Phase 2: y[jj] += r[jj] @ Wg_r (packed f32x2) ----
#pragma unroll 2
        for (int k4 = 0; k4 < 64; k4 += 4) {
            const unsigned long long w0 = S->wsm[(k4 + 0) * 32 + lane];
            const unsigned long long w1 = S->wsm[(k4 + 1) * 32 + lane];
            const unsigned long long w2 = S->wsm[(k4 + 2) * 32 + lane];
            const unsigned long long w3 = S->wsm[(k4 + 3) * 32 + lane];
#pragma unroll
            for (int jj = 0; jj < 8; jj++) {
                const float4 r4 = *(const float4*)&S->Rsm[warp][jj][k4]; // broadcast
                unsigned long long rr;
                DUP2(rr, r4.x); FFMA2(yv[jj], rr, w0);
                DUP2(rr, r4.y); FFMA2(yv[jj], rr, w1);
                DUP2(rr, r4.z); FFMA2(yv[jj], rr, w2);
                DUP2(rr, r4.w); FFMA2(yv[jj], rr, w3);
            }
        }
        __syncwarp();

        // ---- Phase 3: LN + sigmoid gate + accumulate (interleaved chains) ----
        float s1v[8], s2v[8];
#pragma unroll
        for (int jj = 0; jj < 8; jj++) {
            float y_lo, y_hi;
            UNPACK2(y_lo, y_hi, yv[jj]);
            s1v[jj] = y_lo + y_hi;
            s2v[jj] = y_lo * y_lo + y_hi * y_hi;
        }
#pragma unroll
        for (int off = 16; off; off >>= 1) {
#pragma unroll
            for (int jj = 0; jj < 8; jj++) {
                s1v[jj] += __shfl_xor_sync(0xffffffffu, s1v[jj], off);
                s2v[jj] += __shfl_xor_sync(0xffffffffu, s2v[jj], off);
            }
        }
#pragma unroll
        for (int jj = 0; jj < 8; jj++) {
            float y_lo, y_hi;
            UNPACK2(y_lo, y_hi, yv[jj]);
            const float u    = s1v[jj] * (1.f / 64.f);
            const float rstd = rsqrtf(fmaxf(s2v[jj] * (1.f / 64.f) - u * u, 0.f) + LN_EPS);
            const float t_lo = fmaf(gg_lo * (y_lo - u), rstd, beg_lo);
            const float t_hi = fmaf(gg_hi * (y_hi - u), rstd, beg_hi);
            const float gate_lo = 1.f / (1.f + __expf(-t_lo));
            const float gate_hi = 1.f / (1.f + __expf(-t_hi));
            const float hj_lo = S->hsm[warp][jj][lane];        // smem, prefetched
            const float hj_hi = S->hsm[warp][jj][lane + 32];
            if (base + jj < mcount) {            // predicated accumulate only
                acc_lo = fmaf(hj_lo, gate_lo, acc_lo);
                acc_hi = fmaf(hj_hi, gate_hi, acc_hi);
            }
        }
    }

    S->sh_acc[warp][lane]      = acc_lo;
    S->sh_acc[warp][lane + 32] = acc_hi;
    __syncthreads();

    // ---- Block reduce + Pos scale (Pos = 1/mcount if relu(be_a)>0 else 1/N) ----
    if (tid < 64) {
        float s = 0.f;
#pragma unroll
        for (int w = 0; w < 8; w++) s += S->sh_acc[w][tid];
        const float rba   = fmaxf(be_a[0], 0.f);
        const float scale = (rba > 0.f) ? (1.f / (float)(mcount > 0 ? mcount : 1))
                                        : (1.f / (float)NN);
        S->sh_hs[tid] = s * scale;
    }
    __syncthreads();

    // ---- Epilogue: relu(LN(H_sum @ W_w + b_w)) + cn; tanh ----
    if (tid < 64) {
        float y = b_w[tid];
#pragma unroll 16
        for (int k = 0; k < 64; k++)
            y = fmaf(S->sh_hs[k], W_w[k * DD + tid], y);
        S->sh_y[tid] = y;
    }
    __syncthreads();

    if (tid < 64) {
        float s1 = 0.f, s2 = 0.f;
#pragma unroll 16
        for (int k = 0; k < 64; k++) {
            const float v = S->sh_y[k];
            s1 += v;
            s2 += v * v;
        }
        const float u    = s1 * (1.f / 64.f);
        const float rstd = rsqrtf(fmaxf(s2 * (1.f / 64.f) - u * u, 0.f) + LN_EPS);
        const float y    = S->sh_y[tid];
        const float hsum = fmaxf(fmaf(g_w[tid] * (y - u), rstd, be_w[tid]), 0.f);
        const float Cv   = hsum + cn[i * DD + tid];
        const float Hout = h[i * DD + tid] + tanhf(Cv);
        out[i * DD + tid]           = Hout;
        out[NN * DD + i * DD + tid] = Cv;
    }
}

// ---------------------------------------------------------------------------
extern "C" void kernel_launch(void* const* d_in, const int* in_sizes, int n_in,
                              void* d_out, int out_size)
{
    const float* corr = (const float*)d_in[0];
    const int*   nei  = (const int*)d_in[1];
    const float* h    = (const float*)d_in[3];
    const float* cn   = (const float*)d_in[4];
    const float* W_r  = (const float*)d_in[5];
    const float* b_r  = (const float*)d_in[6];
    const float* g_r  = (const float*)d_in[7];
    const float* be_r = (const float*)d_in[8];
    const float* W_g  = (const float*)d_in[9];
    const float* b_g  = (const float*)d_in[10];
    const float* g_g  = (const float*)d_in[11];
    const float* be_g = (const float*)d_in[12];
    const float* be_a = (const float*)d_in[16];
    const float* W_w  = (const float*)d_in[17];
    const float* b_w  = (const float*)d_in[18];
    const float* g_w  = (const float*)d_in[19];
    const float* be_w = (const float*)d_in[20];
    float* out = (float*)d_out;

    const int smem_bytes = (int)sizeof(Smem);
    cudaFuncSetAttribute(gatraj_main_kernel,
                         cudaFuncAttributeMaxDynamicSharedMemorySize, smem_bytes);

    precompute_kernel<<<NN, DD>>>(h, W_g, b_g, W_r, b_r);
    gatraj_main_kernel<<<NN, 256, smem_bytes>>>(corr, nei, h, cn,
                                                W_r, b_r, g_r, be_r,
                                                W_g, g_g, be_g, be_a,
                                                W_w, b_w, g_w, be_w, out);
}

// round 15
// speedup vs baseline: 1.3138x; 1.2112x over previous
#include <cuda_runtime.h>
#include <cstdint>

#define NN 768
#define DD 64
#define LN_EPS 1e-5f

__device__ float g_A[NN * DD];  // h[i] @ W_g[64:128]
__device__ float g_B[NN * DD];  // h[j] @ W_g[128:192] + b_g
__device__ float g_S[9];        // LN(z) moment scalars (scaled by 1/64)

#define CVT_TF32(u, f) asm("cvt.rna.tf32.f32 %0, %1;" : "=r"(u) : "f"(f))
#define MMA_TF32(d0, d1, d2, d3, a0, a1, a2, a3, b0, b1)                  \
    asm volatile(                                                         \
        "mma.sync.aligned.m16n8k8.row.col.f32.tf32.tf32.f32 "             \
        "{%0,%1,%2,%3}, {%4,%5,%6,%7}, {%8,%9}, {%0,%1,%2,%3};"           \
        : "+f"(d0), "+f"(d1), "+f"(d2), "+f"(d3)                          \
        : "r"(a0), "r"(a1), "r"(a2), "r"(a3), "r"(b0), "r"(b1))

// ---------------------------------------------------------------------------
// Precompute A[i,d], B[i,d], and the 9 LN(z) moment scalars
// ---------------------------------------------------------------------------
__global__ __launch_bounds__(DD) void precompute_kernel(
    const float* __restrict__ h,
    const float* __restrict__ W_g,
    const float* __restrict__ b_g,
    const float* __restrict__ W_r,
    const float* __restrict__ b_r)
{
    __shared__ float hs[DD];
    const int i = blockIdx.x;
    const int d = threadIdx.x;
    hs[d] = h[i * DD + d];
    __syncthreads();
    float a = 0.f, b = 0.f;
#pragma unroll 16
    for (int k = 0; k < DD; k++) {
        float hv = hs[k];
        a = fmaf(hv, W_g[(64 + k) * DD + d], a);
        b = fmaf(hv, W_g[(128 + k) * DD + d], b);
    }
    g_A[i * DD + d] = a;
    g_B[i * DD + d] = b + b_g[d];

    if (i == 0) {
        const float w0 = W_r[d], w1 = W_r[64 + d], bb = b_r[d];
        float v[9] = { w0, w1, bb, w0 * w0, w1 * w1, w0 * w1,
                       w0 * bb, w1 * bb, bb * bb };
        __shared__ float red[2][9];
#pragma unroll
        for (int s = 0; s < 9; s++) {
            float x = v[s];
#pragma unroll
            for (int off = 16; off; off >>= 1)
                x += __shfl_xor_sync(0xffffffffu, x, off);
            v[s] = x;
        }
        if ((d & 31) == 0) {
#pragma unroll
            for (int s = 0; s < 9; s++) red[d >> 5][s] = v[s];
        }
        __syncthreads();
        if (d < 9) g_S[d] = (red[0][d] + red[1][d]) * (1.f / 64.f);
    }
}

struct Smem {
    uint32_t Wsm[64 * 72];      // tf32 W[k][n], row stride 72 (conflict-free b-frags)
    uint32_t Rsm[8][16 * 68];   // per-warp tf32 r[pair][k], row stride 68
    float2   csm[NN];           // staged corr row
    float    ggsm[64];
    float    begsm[64];
    int      list[896];
    int      warp_tot[8], warp_off[8], mcount;
    float    sh_acc[8][64];
    float    sh_hs[64], sh_y[64];
};

// ---------------------------------------------------------------------------
// Main kernel: one block per row i; each warp processes chunks of 16 masked
// pairs. Phase 2 = tf32 tensor-core MMA (m16n8k8): D[16x64] = R @ Wg_r.
// Fragment coords: g = lane/4 (pair within half), c = lane%4.
//   D: d0=(g,2c) d1=(g,2c+1) d2=(g+8,2c) d3=(g+8,2c+1), n-tile nt => d+=8nt.
// ---------------------------------------------------------------------------
__global__ __launch_bounds__(256, 2) void gatraj_main_kernel(
    const float* __restrict__ corr,   // [N,N,2]
    const int*   __restrict__ nei,    // [N,N]
    const float* __restrict__ h,      // [N,D]
    const float* __restrict__ cn,     // [N,D]
    const float* __restrict__ W_r,    // [2,D]
    const float* __restrict__ b_r,
    const float* __restrict__ g_r,
    const float* __restrict__ be_r,
    const float* __restrict__ W_g,    // [3D,D] rows 0..63
    const float* __restrict__ g_g,
    const float* __restrict__ be_g,
    const float* __restrict__ be_a,   // [1]
    const float* __restrict__ W_w,    // [D,D]
    const float* __restrict__ b_w,
    const float* __restrict__ g_w,
    const float* __restrict__ be_w,
    float* __restrict__ out)          // [2*N*D]: H_out then C
{
    extern __shared__ char smem_raw[];
    Smem* S = (Smem*)smem_raw;

    const int i    = blockIdx.x;
    const int tid  = threadIdx.x;
    const int warp = tid >> 5;
    const int lane = tid & 31;
    const int g    = lane >> 2;   // 0..7
    const int c    = lane & 3;    // 0..3

    const int* neirow = nei + (size_t)i * NN;
    const float2* corr2 = (const float2*)corr + (size_t)i * NN;

    // ---- Stage corr row ----
    for (int idx = tid; idx < NN; idx += 256)
        S->csm[idx] = corr2[idx];

    // ---- Stage W (rows 0..63 of W_g) as tf32, stride 72 ----
    for (int idx = tid; idx < 64 * 64; idx += 256) {
        const int k = idx >> 6, n = idx & 63;
        uint32_t t;
        CVT_TF32(t, W_g[k * DD + n]);
        S->Wsm[k * 72 + n] = t;
    }
    if (tid < 64) { S->ggsm[tid] = g_g[tid]; S->begsm[tid] = be_g[tid]; }

    // ---- Deterministic compaction of masked j (sorted order), pad to 128 ----
    {
        const int b3 = tid * 3;
        const int m0 = neirow[b3 + 0] > 0;
        const int m1 = neirow[b3 + 1] > 0;
        const int m2 = neirow[b3 + 2] > 0;
        const int cc = m0 + m1 + m2;
        int s = cc;
#pragma unroll
        for (int off = 1; off < 32; off <<= 1) {
            int v = __shfl_up_sync(0xffffffffu, s, off);
            if (lane >= off) s += v;
        }
        if (lane == 31) S->warp_tot[warp] = s;
        __syncthreads();
        if (tid == 0) {
            int run = 0;
#pragma unroll
            for (int w = 0; w < 8; w++) { S->warp_off[w] = run; run += S->warp_tot[w]; }
            S->mcount = run;
        }
        __syncthreads();
        int pos = S->warp_off[warp] + s - cc;
        if (m0) S->list[pos++] = b3 + 0;
        if (m1) S->list[pos++] = b3 + 1;
        if (m2) S->list[pos++] = b3 + 2;
        const int mc  = S->mcount;
        const int pad = (mc + 127) & ~127;
        for (int idx = mc + tid; idx < pad; idx += 256) S->list[idx] = 0;
    }
    __syncthreads();
    const int mcount = S->mcount;

    // ---- Phase-1 per-lane constants (lane owns dims lane, lane+32) ----
    const float wr0_lo = W_r[lane],        wr0_hi = W_r[lane + 32];
    const float wr1_lo = W_r[64 + lane],   wr1_hi = W_r[64 + lane + 32];
    const float br_lo  = b_r[lane],        br_hi  = b_r[lane + 32];
    const float gr_lo  = g_r[lane],        gr_hi  = g_r[lane + 32];
    const float ber_lo = be_r[lane],       ber_hi = be_r[lane + 32];
    const float S0 = g_S[0], S1 = g_S[1], Sb = g_S[2];
    const float Q00 = g_S[3], Q11 = g_S[4], Q01 = g_S[5];
    const float Q0b = g_S[6], Q1b = g_S[7], Qbb = g_S[8];

    // ---- A fragment preload (loop-invariant): afr[nt] = A[i][8nt+2c, +1] ----
    const float2* A2 = (const float2*)g_A + (size_t)i * 32;
    float2 afr[8];
#pragma unroll
    for (int nt = 0; nt < 8; nt++) afr[nt] = A2[4 * nt + c];

    const float2* B2  = (const float2*)g_B;
    const float2* h2  = (const float2*)h;
    const float2* gg2 = (const float2*)S->ggsm;
    const float2* be2 = (const float2*)S->begsm;

    float2 acc[8];
#pragma unroll
    for (int nt = 0; nt < 8; nt++) acc[nt] = make_float2(0.f, 0.f);

    uint32_t* Rw = S->Rsm[warp];

    for (int base = warp * 16; base < mcount; base += 128) {

        // ---- Phase 1: r for 16 pairs (analytic LN), tf32 -> Rsm ----
#pragma unroll 4
        for (int jj = 0; jj < 16; jj++) {
            const int j = S->list[base + jj];
            const float2 cc = S->csm[j];
            const float z_lo = fmaf(cc.x, wr0_lo, fmaf(cc.y, wr1_lo, br_lo));
            const float z_hi = fmaf(cc.x, wr0_hi, fmaf(cc.y, wr1_hi, br_hi));
            const float u   = fmaf(cc.x, S0, fmaf(cc.y, S1, Sb));
            const float ez2 = fmaf(cc.x * cc.x, Q00,
                              fmaf(cc.y * cc.y, Q11,
                              fmaf(2.f * cc.x * cc.y, Q01,
                              fmaf(2.f * cc.x, Q0b,
                              fmaf(2.f * cc.y, Q1b, Qbb)))));
            const float rstd = rsqrtf(fmaxf(ez2 - u * u, 0.f) + LN_EPS);
            const float r_lo = fmaxf(fmaf(gr_lo * (z_lo - u), rstd, ber_lo), 0.f);
            const float r_hi = fmaxf(fmaf(gr_hi * (z_hi - u), rstd, ber_hi), 0.f);
            uint32_t tlo, thi;
            CVT_TF32(tlo, r_lo);
            CVT_TF32(thi, r_hi);
            Rw[jj * 68 + lane]      = tlo;
            Rw[jj * 68 + lane + 32] = thi;
        }
        __syncwarp();

        const int jlo = S->list[base + g];
        const int jhi = S->list[base + g + 8];

        // ---- Issue B loads early (hidden under MMA) ----
        float2 Bl[8], Bh[8];
#pragma unroll
        for (int nt = 0; nt < 8; nt++) {
            Bl[nt] = B2[(size_t)jlo * 32 + 4 * nt + c];
            Bh[nt] = B2[(size_t)jhi * 32 + 4 * nt + c];
        }

        // ---- Phase 2: D = R @ W via tf32 MMA ----
        float d0[8], d1[8], d2[8], d3[8];
#pragma unroll
        for (int nt = 0; nt < 8; nt++) { d0[nt] = d1[nt] = d2[nt] = d3[nt] = 0.f; }
#pragma unroll
        for (int kt = 0; kt < 8; kt++) {
            const uint32_t a0 = Rw[g * 68 + 8 * kt + c];            // (g,    k)
            const uint32_t a1 = Rw[(g + 8) * 68 + 8 * kt + c];      // (g+8,  k)
            const uint32_t a2 = Rw[g * 68 + 8 * kt + c + 4];        // (g,    k+4)
            const uint32_t a3 = Rw[(g + 8) * 68 + 8 * kt + c + 4];  // (g+8,  k+4)
            const uint32_t* Wk0 = &S->Wsm[(8 * kt + c) * 72];
            const uint32_t* Wk1 = &S->Wsm[(8 * kt + c + 4) * 72];
#pragma unroll
            for (int nt = 0; nt < 8; nt++) {
                const uint32_t b0 = Wk0[8 * nt + g];
                const uint32_t b1 = Wk1[8 * nt + g];
                MMA_TF32(d0[nt], d1[nt], d2[nt], d3[nt],
                         a0, a1, a2, a3, b0, b1);
            }
        }

        // ---- Phase 3: y = D + A + B; LN stats (4-lane groups, 2 shuffles) ----
        float s1l = 0.f, s2l = 0.f, s1h = 0.f, s2h = 0.f;
#pragma unroll
        for (int nt = 0; nt < 8; nt++) {
            const float yl0 = d0[nt] + afr[nt].x + Bl[nt].x;
            const float yl1 = d1[nt] + afr[nt].y + Bl[nt].y;
            const float yh0 = d2[nt] + afr[nt].x + Bh[nt].x;
            const float yh1 = d3[nt] + afr[nt].y + Bh[nt].y;
            d0[nt] = yl0; d1[nt] = yl1; d2[nt] = yh0; d3[nt] = yh1;
            s1l += yl0 + yl1; s2l = fmaf(yl0, yl0, fmaf(yl1, yl1, s2l));
            s1h += yh0 + yh1; s2h = fmaf(yh0, yh0, fmaf(yh1, yh1, s2h));
        }
        s1l += __shfl_xor_sync(0xffffffffu, s1l, 1);
        s2l += __shfl_xor_sync(0xffffffffu, s2l, 1);
        s1h += __shfl_xor_sync(0xffffffffu, s1h, 1);
        s2h += __shfl_xor_sync(0xffffffffu, s2h, 1);
        s1l += __shfl_xor_sync(0xffffffffu, s1l, 2);
        s2l += __shfl_xor_sync(0xffffffffu, s2l, 2);
        s1h += __shfl_xor_sync(0xffffffffu, s1h, 2);
        s2h += __shfl_xor_sync(0xffffffffu, s2h, 2);

        // ---- h loads (hidden under LN/sigmoid math) ----
        float2 Hl[8], Hh[8];
#pragma unroll
        for (int nt = 0; nt < 8; nt++) {
            Hl[nt] = h2[(size_t)jlo * 32 + 4 * nt + c];
            Hh[nt] = h2[(size_t)jhi * 32 + 4 * nt + c];
        }

        const float ul    = s1l * (1.f / 64.f);
        const float rstdl = rsqrtf(fmaxf(s2l * (1.f / 64.f) - ul * ul, 0.f) + LN_EPS);
        const float uh    = s1h * (1.f / 64.f);
        const float rstdh = rsqrtf(fmaxf(s2h * (1.f / 64.f) - uh * uh, 0.f) + LN_EPS);
        const bool okl = (base + g)     < mcount;
        const bool okh = (base + g + 8) < mcount;

#pragma unroll
        for (int nt = 0; nt < 8; nt++) {
            const float2 gg = gg2[4 * nt + c];
            const float2 be = be2[4 * nt + c];
            float t;
            t = fmaf(gg.x * (d0[nt] - ul), rstdl, be.x);
            const float gl0 = 1.f / (1.f + __expf(-t));
            t = fmaf(gg.y * (d1[nt] - ul), rstdl, be.y);
            const float gl1 = 1.f / (1.f + __expf(-t));
            t = fmaf(gg.x * (d2[nt] - uh), rstdh, be.x);
            const float gh0 = 1.f / (1.f + __expf(-t));
            t = fmaf(gg.y * (d3[nt] - uh), rstdh, be.y);
            const float gh1 = 1.f / (1.f + __expf(-t));
            if (okl) {
                acc[nt].x = fmaf(Hl[nt].x, gl0, acc[nt].x);
                acc[nt].y = fmaf(Hl[nt].y, gl1, acc[nt].y);
            }
            if (okh) {
                acc[nt].x = fmaf(Hh[nt].x, gh0, acc[nt].x);
                acc[nt].y = fmaf(Hh[nt].y, gh1, acc[nt].y);
            }
        }
        __syncwarp();   // Rsm reads complete before next chunk's writes
    }

    // ---- Reduce acc across the 8 groups (lanes differing in bits 2..4) ----
#pragma unroll
    for (int nt = 0; nt < 8; nt++) {
#pragma unroll
        for (int off = 4; off <= 16; off <<= 1) {
            acc[nt].x += __shfl_xor_sync(0xffffffffu, acc[nt].x, off);
            acc[nt].y += __shfl_xor_sync(0xffffffffu, acc[nt].y, off);
        }
        if (g == 0) {
            S->sh_acc[warp][8 * nt + 2 * c]     = acc[nt].x;
            S->sh_acc[warp][8 * nt + 2 * c + 1] = acc[nt].y;
        }
    }
    __syncthreads();

    // ---- Block reduce + Pos scale (Pos = 1/mcount if relu(be_a)>0 else 1/N) ----
    if (tid < 64) {
        float s = 0.f;
#pragma unroll
        for (int w = 0; w < 8; w++) s += S->sh_acc[w][tid];
        const float rba   = fmaxf(be_a[0], 0.f);
        const float scale = (rba > 0.f) ? (1.f / (float)(mcount > 0 ? mcount : 1))
                                        : (1.f / (float)NN);
        S->sh_hs[tid] = s * scale;
    }
    __syncthreads();

    // ---- Epilogue: relu(LN(H_sum @ W_w + b_w)) + cn; tanh ----
    if (tid < 64) {
        float y = b_w[tid];
#pragma unroll 16
        for (int k = 0; k < 64; k++)
            y = fmaf(S->sh_hs[k], W_w[k * DD + tid], y);
        S->sh_y[tid] = y;
    }
    __syncthreads();

    if (tid < 64) {
        float s1 = 0.f, s2 = 0.f;
#pragma unroll 16
        for (int k = 0; k < 64; k++) {
            const float v = S->sh_y[k];
            s1 += v;
            s2 += v * v;
        }
        const float u    = s1 * (1.f / 64.f);
        const float rstd = rsqrtf(fmaxf(s2 * (1.f / 64.f) - u * u, 0.f) + LN_EPS);
        const float y    = S->sh_y[tid];
        const float hsum = fmaxf(fmaf(g_w[tid] * (y - u), rstd, be_w[tid]), 0.f);
        const float Cv   = hsum + cn[i * DD + tid];
        const float Hout = h[i * DD + tid] + tanhf(Cv);
        out[i * DD + tid]           = Hout;
        out[NN * DD + i * DD + tid] = Cv;
    }
}

// ---------------------------------------------------------------------------
extern "C" void kernel_launch(void* const* d_in, const int* in_sizes, int n_in,
                              void* d_out, int out_size)
{
    const float* corr = (const float*)d_in[0];
    const int*   nei  = (const int*)d_in[1];
    const float* h    = (const float*)d_in[3];
    const float* cn   = (const float*)d_in[4];
    const float* W_r  = (const float*)d_in[5];
    const float* b_r  = (const float*)d_in[6];
    const float* g_r  = (const float*)d_in[7];
    const float* be_r = (const float*)d_in[8];
    const float* W_g  = (const float*)d_in[9];
    const float* b_g  = (const float*)d_in[10];
    const float* g_g  = (const float*)d_in[11];
    const float* be_g = (const float*)d_in[12];
    const float* be_a = (const float*)d_in[16];
    const float* W_w  = (const float*)d_in[17];
    const float* b_w  = (const float*)d_in[18];
    const float* g_w  = (const float*)d_in[19];
    const float* be_w = (const float*)d_in[20];
    float* out = (float*)d_out;

    const int smem_bytes = (int)sizeof(Smem);
    cudaFuncSetAttribute(gatraj_main_kernel,
                         cudaFuncAttributeMaxDynamicSharedMemorySize, smem_bytes);

    precompute_kernel<<<NN, DD>>>(h, W_g, b_g, W_r, b_r);
    gatraj_main_kernel<<<NN, 256, smem_bytes>>>(corr, nei, h, cn,
                                                W_r, b_r, g_r, be_r,
                                                W_g, g_g, be_g, be_a,
                                                W_w, b_w, g_w, be_w, out);
}

// round 17
// speedup vs baseline: 1.3405x; 1.0203x over previous
#include <cuda_runtime.h>
#include <cstdint>

#define NN 768
#define DD 64
#define LN_EPS 1e-5f

__device__ float g_A[NN * DD];  // h[i] @ W_g[64:128]
__device__ float g_B[NN * DD];  // h[j] @ W_g[128:192] + b_g
__device__ float g_S[9];        // LN(z) moment scalars (scaled by 1/64)

#define CVT_TF32(u, f) asm("cvt.rna.tf32.f32 %0, %1;" : "=r"(u) : "f"(f))
#define MMA_TF32(d0, d1, d2, d3, a0, a1, a2, a3, b0, b1)                  \
    asm volatile(                                                         \
        "mma.sync.aligned.m16n8k8.row.col.f32.tf32.tf32.f32 "             \
        "{%0,%1,%2,%3}, {%4,%5,%6,%7}, {%8,%9}, {%0,%1,%2,%3};"           \
        : "+f"(d0), "+f"(d1), "+f"(d2), "+f"(d3)                          \
        : "r"(a0), "r"(a1), "r"(a2), "r"(a3), "r"(b0), "r"(b1))

// ---------------------------------------------------------------------------
// Precompute A[i,d], B[i,d], and the 9 LN(z) moment scalars
// ---------------------------------------------------------------------------
__global__ __launch_bounds__(DD) void precompute_kernel(
    const float* __restrict__ h,
    const float* __restrict__ W_g,
    const float* __restrict__ b_g,
    const float* __restrict__ W_r,
    const float* __restrict__ b_r)
{
    __shared__ float hs[DD];
    const int i = blockIdx.x;
    const int d = threadIdx.x;
    hs[d] = h[i * DD + d];
    __syncthreads();
    float a = 0.f, b = 0.f;
#pragma unroll 16
    for (int k = 0; k < DD; k++) {
        float hv = hs[k];
        a = fmaf(hv, W_g[(64 + k) * DD + d], a);
        b = fmaf(hv, W_g[(128 + k) * DD + d], b);
    }
    g_A[i * DD + d] = a;
    g_B[i * DD + d] = b + b_g[d];

    if (i == 0) {
        const float w0 = W_r[d], w1 = W_r[64 + d], bb = b_r[d];
        float v[9] = { w0, w1, bb, w0 * w0, w1 * w1, w0 * w1,
                       w0 * bb, w1 * bb, bb * bb };
        __shared__ float red[2][9];
#pragma unroll
        for (int s = 0; s < 9; s++) {
            float x = v[s];
#pragma unroll
            for (int off = 16; off; off >>= 1)
                x += __shfl_xor_sync(0xffffffffu, x, off);
            v[s] = x;
        }
        if ((d & 31) == 0) {
#pragma unroll
            for (int s = 0; s < 9; s++) red[d >> 5][s] = v[s];
        }
        __syncthreads();
        if (d < 9) g_S[d] = (red[0][d] + red[1][d]) * (1.f / 64.f);
    }
}

struct Smem {
    uint32_t Wsm[64 * 68];      // tf32 W[k][n'], n' = (n&7)*8 + (n>>3), stride 68
                                // (68 words = 272 B: 16B-aligned rows for LDS.128;
                                //  start banks (4c+8g)%32 cover 8 residues x4 lanes)
    uint32_t Rsm[8][16 * 68];   // per-warp tf32 r[pair][k], row stride 68
    float2   csm[NN];           // staged corr row
    float    ggsm[64];
    float    begsm[64];
    int      list[896];
    int      warp_tot[8], warp_off[8], mcount;
    float    sh_acc[8][64];
    float    sh_hs[64], sh_y[64];
};

// ---------------------------------------------------------------------------
// Main kernel: one block per row i; each warp processes chunks of 16 masked
// pairs. Phase 2 = tf32 tensor-core MMA (m16n8k8): D[16x64] = R @ Wg_r.
// Fragment coords: g = lane/4, c = lane%4.
//   D: d0=(g,2c) d1=(g,2c+1) d2=(g+8,2c) d3=(g+8,2c+1), n-tile nt => n+=8nt.
// B-fragments vectorized: W stored g-major in n => 4 x LDS.128 per kt.
// Phase-1 LN stats computed lane-parallel (lane jj owns pair jj) + SHFL bcast.
// ---------------------------------------------------------------------------
__global__ __launch_bounds__(256, 2) void gatraj_main_kernel(
    const float* __restrict__ corr,   // [N,N,2]
    const int*   __restrict__ nei,    // [N,N]
    const float* __restrict__ h,      // [N,D]
    const float* __restrict__ cn,     // [N,D]
    const float* __restrict__ W_r,    // [2,D]
    const float* __restrict__ b_r,
    const float* __restrict__ g_r,
    const float* __restrict__ be_r,
    const float* __restrict__ W_g,    // [3D,D] rows 0..63
    const float* __restrict__ g_g,
    const float* __restrict__ be_g,
    const float* __restrict__ be_a,   // [1]
    const float* __restrict__ W_w,    // [D,D]
    const float* __restrict__ b_w,
    const float* __restrict__ g_w,
    const float* __restrict__ be_w,
    float* __restrict__ out)          // [2*N*D]: H_out then C
{
    extern __shared__ char smem_raw[];
    Smem* S = (Smem*)smem_raw;

    const int i    = blockIdx.x;
    const int tid  = threadIdx.x;
    const int warp = tid >> 5;
    const int lane = tid & 31;
    const int g    = lane >> 2;   // 0..7
    const int c    = lane & 3;    // 0..3

    const int* neirow = nei + (size_t)i * NN;
    const float2* corr2 = (const float2*)corr + (size_t)i * NN;

    // ---- Stage corr row ----
    for (int idx = tid; idx < NN; idx += 256)
        S->csm[idx] = corr2[idx];

    // ---- Stage W (rows 0..63 of W_g) as tf32, g-major n, stride 68 ----
    for (int idx = tid; idx < 64 * 64; idx += 256) {
        const int k = idx >> 6, n = idx & 63;
        uint32_t t;
        CVT_TF32(t, W_g[k * DD + n]);
        S->Wsm[k * 68 + ((n & 7) << 3) + (n >> 3)] = t;
    }
    if (tid < 64) { S->ggsm[tid] = g_g[tid]; S->begsm[tid] = be_g[tid]; }

    // ---- Deterministic compaction of masked j (sorted order), pad to 128 ----
    {
        const int b3 = tid * 3;
        const int m0 = neirow[b3 + 0] > 0;
        const int m1 = neirow[b3 + 1] > 0;
        const int m2 = neirow[b3 + 2] > 0;
        const int cc = m0 + m1 + m2;
        int s = cc;
#pragma unroll
        for (int off = 1; off < 32; off <<= 1) {
            int v = __shfl_up_sync(0xffffffffu, s, off);
            if (lane >= off) s += v;
        }
        if (lane == 31) S->warp_tot[warp] = s;
        __syncthreads();
        if (tid == 0) {
            int run = 0;
#pragma unroll
            for (int w = 0; w < 8; w++) { S->warp_off[w] = run; run += S->warp_tot[w]; }
            S->mcount = run;
        }
        __syncthreads();
        int pos = S->warp_off[warp] + s - cc;
        if (m0) S->list[pos++] = b3 + 0;
        if (m1) S->list[pos++] = b3 + 1;
        if (m2) S->list[pos++] = b3 + 2;
        const int mc  = S->mcount;
        const int pad = (mc + 127) & ~127;
        for (int idx = mc + tid; idx < pad; idx += 256) S->list[idx] = 0;
    }
    __syncthreads();
    const int mcount = S->mcount;

    // ---- Phase-1 per-lane constants (lane owns dims lane, lane+32) ----
    const float wr0_lo = W_r[lane],        wr0_hi = W_r[lane + 32];
    const float wr1_lo = W_r[64 + lane],   wr1_hi = W_r[64 + lane + 32];
    const float br_lo  = b_r[lane],        br_hi  = b_r[lane + 32];
    const float gr_lo  = g_r[lane],        gr_hi  = g_r[lane + 32];
    const float ber_lo = be_r[lane],       ber_hi = be_r[lane + 32];
    const float S0 = g_S[0], S1 = g_S[1], Sb = g_S[2];
    const float Q00 = g_S[3], Q11 = g_S[4], Q01 = g_S[5];
    const float Q0b = g_S[6], Q1b = g_S[7], Qbb = g_S[8];

    // ---- A fragment preload (loop-invariant): afr[nt] = A[i][8nt+2c, +1] ----
    const float2* A2 = (const float2*)g_A + (size_t)i * 32;
    float2 afr[8];
#pragma unroll
    for (int nt = 0; nt < 8; nt++) afr[nt] = A2[4 * nt + c];

    const float2* B2  = (const float2*)g_B;
    const float2* h2  = (const float2*)h;
    const float2* gg2 = (const float2*)S->ggsm;
    const float2* be2 = (const float2*)S->begsm;

    float2 acc[8];
#pragma unroll
    for (int nt = 0; nt < 8; nt++) acc[nt] = make_float2(0.f, 0.f);

    uint32_t* Rw = S->Rsm[warp];

    for (int base = warp * 16; base < mcount; base += 128) {

        // ---- Phase 1a: lane-parallel LN stats (lane jj owns pair jj) ----
        float um, rstdm;
        {
            const int jm = S->list[base + (lane & 15)];
            const float2 cm = S->csm[jm];
            um = fmaf(cm.x, S0, fmaf(cm.y, S1, Sb));
            const float ez2 = fmaf(cm.x * cm.x, Q00,
                              fmaf(cm.y * cm.y, Q11,
                              fmaf(2.f * cm.x * cm.y, Q01,
                              fmaf(2.f * cm.x, Q0b,
                              fmaf(2.f * cm.y, Q1b, Qbb)))));
            rstdm = rsqrtf(fmaxf(ez2 - um * um, 0.f) + LN_EPS);
        }

        // ---- Phase 1b: r for 16 pairs -> Rsm (tf32) ----
#pragma unroll 4
        for (int jj = 0; jj < 16; jj++) {
            const int j = S->list[base + jj];
            const float2 cc = S->csm[j];
            const float u    = __shfl_sync(0xffffffffu, um,    jj);
            const float rstd = __shfl_sync(0xffffffffu, rstdm, jj);
            const float z_lo = fmaf(cc.x, wr0_lo, fmaf(cc.y, wr1_lo, br_lo));
            const float z_hi = fmaf(cc.x, wr0_hi, fmaf(cc.y, wr1_hi, br_hi));
            const float grr_lo = gr_lo * rstd;
            const float grr_hi = gr_hi * rstd;
            const float r_lo = fmaxf(fmaf(z_lo - u, grr_lo, ber_lo), 0.f);
            const float r_hi = fmaxf(fmaf(z_hi - u, grr_hi, ber_hi), 0.f);
            uint32_t tlo, thi;
            CVT_TF32(tlo, r_lo);
            CVT_TF32(thi, r_hi);
            Rw[jj * 68 + lane]      = tlo;
            Rw[jj * 68 + lane + 32] = thi;
        }
        __syncwarp();

        const int jlo = S->list[base + g];
        const int jhi = S->list[base + g + 8];

        // ---- Issue B loads early (hidden under MMA) ----
        float2 Bl[8], Bh[8];
#pragma unroll
        for (int nt = 0; nt < 8; nt++) {
            Bl[nt] = B2[(size_t)jlo * 32 + 4 * nt + c];
            Bh[nt] = B2[(size_t)jhi * 32 + 4 * nt + c];
        }

        // ---- Phase 2: D = R @ W via tf32 MMA (vectorized b-frags) ----
        float d0[8], d1[8], d2[8], d3[8];
#pragma unroll
        for (int nt = 0; nt < 8; nt++) { d0[nt] = d1[nt] = d2[nt] = d3[nt] = 0.f; }
#pragma unroll
        for (int kt = 0; kt < 8; kt++) {
            const uint32_t a0 = Rw[g * 68 + 8 * kt + c];            // (g,    k)
            const uint32_t a1 = Rw[(g + 8) * 68 + 8 * kt + c];      // (g+8,  k)
            const uint32_t a2 = Rw[g * 68 + 8 * kt + c + 4];        // (g,    k+4)
            const uint32_t a3 = Rw[(g + 8) * 68 + 8 * kt + c + 4];  // (g+8,  k+4)
            const int k0 = 8 * kt + c;
            const int k1 = k0 + 4;
            // b0 for nt=0..3 / 4..7 (row k0), b1 likewise (row k1)
            const uint4 q0 = *(const uint4*)&S->Wsm[k0 * 68 + 8 * g];
            const uint4 q1 = *(const uint4*)&S->Wsm[k0 * 68 + 8 * g + 4];
            const uint4 q2 = *(const uint4*)&S->Wsm[k1 * 68 + 8 * g];
            const uint4 q3 = *(const uint4*)&S->Wsm[k1 * 68 + 8 * g + 4];
            MMA_TF32(d0[0], d1[0], d2[0], d3[0], a0, a1, a2, a3, q0.x, q2.x);
            MMA_TF32(d0[1], d1[1], d2[1], d3[1], a0, a1, a2, a3, q0.y, q2.y);
            MMA_TF32(d0[2], d1[2], d2[2], d3[2], a0, a1, a2, a3, q0.z, q2.z);
            MMA_TF32(d0[3], d1[3], d2[3], d3[3], a0, a1, a2, a3, q0.w, q2.w);
            MMA_TF32(d0[4], d1[4], d2[4], d3[4], a0, a1, a2, a3, q1.x, q3.x);
            MMA_TF32(d0[5], d1[5], d2[5], d3[5], a0, a1, a2, a3, q1.y, q3.y);
            MMA_TF32(d0[6], d1[6], d2[6], d3[6], a0, a1, a2, a3, q1.z, q3.z);
            MMA_TF32(d0[7], d1[7], d2[7], d3[7], a0, a1, a2, a3, q1.w, q3.w);
        }

        // ---- Phase 3: y = D + A + B; LN stats (4-lane groups, 2 shuffles) ----
        float s1l = 0.f, s2l = 0.f, s1h = 0.f, s2h = 0.f;
#pragma unroll
        for (int nt = 0; nt < 8; nt++) {
            const float yl0 = d0[nt] + afr[nt].x + Bl[nt].x;
            const float yl1 = d1[nt] + afr[nt].y + Bl[nt].y;
            const float yh0 = d2[nt] + afr[nt].x + Bh[nt].x;
            const float yh1 = d3[nt] + afr[nt].y + Bh[nt].y;
            d0[nt] = yl0; d1[nt] = yl1; d2[nt] = yh0; d3[nt] = yh1;
            s1l += yl0 + yl1; s2l = fmaf(yl0, yl0, fmaf(yl1, yl1, s2l));
            s1h += yh0 + yh1; s2h = fmaf(yh0, yh0, fmaf(yh1, yh1, s2h));
        }
        s1l += __shfl_xor_sync(0xffffffffu, s1l, 1);
        s2l += __shfl_xor_sync(0xffffffffu, s2l, 1);
        s1h += __shfl_xor_sync(0xffffffffu, s1h, 1);
        s2h += __shfl_xor_sync(0xffffffffu, s2h, 1);
        s1l += __shfl_xor_sync(0xffffffffu, s1l, 2);
        s2l += __shfl_xor_sync(0xffffffffu, s2l, 2);
        s1h += __shfl_xor_sync(0xffffffffu, s1h, 2);
        s2h += __shfl_xor_sync(0xffffffffu, s2h, 2);

        // ---- h loads (hidden under LN/sigmoid math) ----
        float2 Hl[8], Hh[8];
#pragma unroll
        for (int nt = 0; nt < 8; nt++) {
            Hl[nt] = h2[(size_t)jlo * 32 + 4 * nt + c];
            Hh[nt] = h2[(size_t)jhi * 32 + 4 * nt + c];
        }

        const float ul    = s1l * (1.f / 64.f);
        const float rstdl = rsqrtf(fmaxf(s2l * (1.f / 64.f) - ul * ul, 0.f) + LN_EPS);
        const float uh    = s1h * (1.f / 64.f);
        const float rstdh = rsqrtf(fmaxf(s2h * (1.f / 64.f) - uh * uh, 0.f) + LN_EPS);
        const bool okl = (base + g)     < mcount;
        const bool okh = (base + g + 8) < mcount;

#pragma unroll
        for (int nt = 0; nt < 8; nt++) {
            const float2 gg = gg2[4 * nt + c];
            const float2 be = be2[4 * nt + c];
            float t;
            t = fmaf(gg.x * (d0[nt] - ul), rstdl, be.x);
            const float gl0 = 1.f / (1.f + __expf(-t));
            t = fmaf(gg.y * (d1[nt] - ul), rstdl, be.y);
            const float gl1 = 1.f / (1.f + __expf(-t));
            t = fmaf(gg.x * (d2[nt] - uh), rstdh, be.x);
            const float gh0 = 1.f / (1.f + __expf(-t));
            t = fmaf(gg.y * (d3[nt] - uh), rstdh, be.y);
            const float gh1 = 1.f / (1.f + __expf(-t));
            if (okl) {
                acc[nt].x = fmaf(Hl[nt].x, gl0, acc[nt].x);
                acc[nt].y = fmaf(Hl[nt].y, gl1, acc[nt].y);
            }
            if (okh) {
                acc[nt].x = fmaf(Hh[nt].x, gh0, acc[nt].x);
                acc[nt].y = fmaf(Hh[nt].y, gh1, acc[nt].y);
            }
        }
        __syncwarp();   // Rsm reads complete before next chunk's writes
    }

    // ---- Reduce acc across the 8 groups (lanes differing in bits 2..4) ----
#pragma unroll
    for (int nt = 0; nt < 8; nt++) {
#pragma unroll
        for (int off = 4; off <= 16; off <<= 1) {
            acc[nt].x += __shfl_xor_sync(0xffffffffu, acc[nt].x, off);
            acc[nt].y += __shfl_xor_sync(0xffffffffu, acc[nt].y, off);
        }
        if (g == 0) {
            S->sh_acc[warp][8 * nt + 2 * c]     = acc[nt].x;
            S->sh_acc[warp][8 * nt + 2 * c + 1] = acc[nt].y;
        }
    }
    __syncthreads();

    // ---- Block reduce + Pos scale (Pos = 1/mcount if relu(be_a)>0 else 1/N) ----
    if (tid < 64) {
        float s = 0.f;
#pragma unroll
        for (int w = 0; w < 8; w++) s += S->sh_acc[w][tid];
        const float rba   = fmaxf(be_a[0], 0.f);
        const float scale = (rba > 0.f) ? (1.f / (float)(mcount > 0 ? mcount : 1))
                                        : (1.f / (float)NN);
        S->sh_hs[tid] = s * scale;
    }
    __syncthreads();

    // ---- Epilogue: relu(LN(H_sum @ W_w + b_w)) + cn; tanh ----
    if (tid < 64) {
        float y = b_w[tid];
#pragma unroll 16
        for (int k = 0; k < 64; k++)
            y = fmaf(S->sh_hs[k], W_w[k * DD + tid], y);
        S->sh_y[tid] = y;
    }
    __syncthreads();

    if (tid < 64) {
        float s1 = 0.f, s2 = 0.f;
#pragma unroll 16
        for (int k = 0; k < 64; k++) {
            const float v = S->sh_y[k];
            s1 += v;
            s2 += v * v;
        }
        const float u    = s1 * (1.f / 64.f);
        const float rstd = rsqrtf(fmaxf(s2 * (1.f / 64.f) - u * u, 0.f) + LN_EPS);
        const float y    = S->sh_y[tid];
        const float hsum = fmaxf(fmaf(g_w[tid] * (y - u), rstd, be_w[tid]), 0.f);
        const float Cv   = hsum + cn[i * DD + tid];
        const float Hout = h[i * DD + tid] + tanhf(Cv);
        out[i * DD + tid]           = Hout;
        out[NN * DD + i * DD + tid] = Cv;
    }
}

// ---------------------------------------------------------------------------
extern "C" void kernel_launch(void* const* d_in, const int* in_sizes, int n_in,
                              void* d_out, int out_size)
{
    const float* corr = (const float*)d_in[0];
    const int*   nei  = (const int*)d_in[1];
    const float* h    = (const float*)d_in[3];
    const float* cn   = (const float*)d_in[4];
    const float* W_r  = (const float*)d_in[5];
    const float* b_r  = (const float*)d_in[6];
    const float* g_r  = (const float*)d_in[7];
    const float* be_r = (const float*)d_in[8];
    const float* W_g  = (const float*)d_in[9];
    const float* b_g  = (const float*)d_in[10];
    const float* g_g  = (const float*)d_in[11];
    const float* be_g = (const float*)d_in[12];
    const float* be_a = (const float*)d_in[16];
    const float* W_w  = (const float*)d_in[17];
    const float* b_w  = (const float*)d_in[18];
    const float* g_w  = (const float*)d_in[19];
    const float* be_w = (const float*)d_in[20];
    float* out = (float*)d_out;

    const int smem_bytes = (int)sizeof(Smem);
    cudaFuncSetAttribute(gatraj_main_kernel,
                         cudaFuncAttributeMaxDynamicSharedMemorySize, smem_bytes);

    precompute_kernel<<<NN, DD>>>(h, W_g, b_g, W_r, b_r);
    gatraj_main_kernel<<<NN, 256, smem_bytes>>>(corr, nei, h, cn,
                                                W_r, b_r, g_r, be_r,
                                                W_g, g_g, be_g, be_a,
                                                W_w, b_w, g_w, be_w, out);
}